// round 15
// baseline (speedup 1.0000x reference)
#include <cuda_runtime.h>
#include <cuda_bf16.h>

// Batched per-sample MLP: B=32, 1024 -> 2048 (relu) -> 2048 (relu) -> 1024 (linear)
// HBM-bound GEMV chain at the achievable streaming ceiling (~6.2 TB/s per kernel).
// Round 14: R13 core (coarse PDL chaining, fused zero jobs, no memsets, __ldcs
// streaming, unroll 16, float4 vector atomics) + halved split-K depth for
// layers 2/3 (KS 16->8, 32->16): atomic RMW traffic and per-CTA overhead halve
// while the streaming rate (proven invariant to split depth) is unchanged.

#define BATCH 32
#define L0 1024
#define L1 2048
#define L2 2048
#define L3 1024

// Per-sample param layout offsets (fp32 elements)
#define W1_OFF 0LL
#define B1_OFF (W1_OFF + (long long)L0 * L1)          // 2097152
#define W2_OFF (B1_OFF + L1)                          // 2099200
#define B2_OFF (W2_OFF + (long long)L1 * L2)          // 6293504
#define W3_OFF (B2_OFF + L2)                          // 6295552
#define B3_OFF (W3_OFF + (long long)L2 * L3)          // 8392704
#define P_LEN  (B3_OFF + L3)                          // 8393728

// Intermediate activations (device globals — zero-initialized at load,
// re-zeroed each pass for graph replay correctness).
__device__ float g_act1[BATCH * L1];
__device__ float g_act2[BATCH * L2];

// One CTA: BLOCK threads, each computing 4 consecutive outputs over a CHUNK of
// the input dimension; partial sums accumulated into y via one float4 atomicAdd.
// RELU_IN : apply relu to x_in while staging (x_in holds pre-activation sums).
// ZERO_N  : element count of z_buf for ks==0 CTAs to zero.
// PDL     : call cudaGridDependencySynchronize() before touching x_in.
// ZERO_POST: zero z_buf AFTER the dependency sync (z_buf is read by the
//            predecessor, so the zero must wait for it — layer3 zeroing act1).
template <int IN, int OUT, int CHUNK, int BLOCK, bool RELU_IN, int ZERO_N,
          bool PDL, bool ZERO_POST>
__global__ void __launch_bounds__(BLOCK)
mlp_layer_splitk(const float* __restrict__ params,
                 long long w_off, long long b_off,
                 const float* __restrict__ x_in,
                 float* __restrict__ y_out,
                 float* __restrict__ z_buf)
{
    __shared__ float sx[CHUNK];

    const int b   = blockIdx.y;
    const int ks  = blockIdx.z;
    const int i0  = ks * CHUNK;
    const int o4  = (blockIdx.x * BLOCK + threadIdx.x) * 4;

    const int nzeroers = gridDim.x * BATCH;
    const int cta_id   = blockIdx.y * gridDim.x + blockIdx.x;

    // Pre-sync side job: zero a buffer the predecessor does NOT read
    // (runs during the predecessor's drain wave under PDL).
    if (ZERO_N > 0 && !ZERO_POST && ks == 0) {
        float4* zb = reinterpret_cast<float4*>(z_buf);
        const int total4 = ZERO_N / 4;
        for (int idx = cta_id * BLOCK + threadIdx.x; idx < total4;
             idx += nzeroers * BLOCK)
            zb[idx] = make_float4(0.f, 0.f, 0.f, 0.f);
    }

    // Pre-sync: bias prefetch (pure input, independent of predecessor).
    float ax = 0.f, ay = 0.f, az = 0.f, aw = 0.f;
    if (ks == 0) {
        const float* __restrict__ Bv = params + (long long)b * P_LEN + b_off + o4;
        float4 bv = __ldg(reinterpret_cast<const float4*>(Bv));
        ax = bv.x; ay = bv.y; az = bv.z; aw = bv.w;
    }

#if defined(__CUDA_ARCH__) && (__CUDA_ARCH__ >= 900)
    if (PDL) cudaGridDependencySynchronize();
#endif

    // Post-sync zero job (buffer was read by the predecessor; sync makes it safe).
    if (ZERO_N > 0 && ZERO_POST && ks == 0) {
        float4* zb = reinterpret_cast<float4*>(z_buf);
        const int total4 = ZERO_N / 4;
        for (int idx = cta_id * BLOCK + threadIdx.x; idx < total4;
             idx += nzeroers * BLOCK)
            zb[idx] = make_float4(0.f, 0.f, 0.f, 0.f);
    }

    // Stage this CTA's input chunk, applying relu if needed.
    const float* __restrict__ xb = x_in + (long long)b * IN + i0;
    for (int i = threadIdx.x; i < CHUNK; i += BLOCK) {
        float v = __ldg(&xb[i]);
        if (RELU_IN) v = fmaxf(v, 0.0f);
        sx[i] = v;
    }
    __syncthreads();

    const float* __restrict__ Wb =
        params + (long long)b * P_LEN + w_off + (long long)i0 * OUT + o4;

    // Inner loop: one streaming LDG.128 per thread per i (512B/warp).
    // __ldcs: W is read exactly once — evict-first keeps L2 for act/bias/atomics.
    #pragma unroll 16
    for (int i = 0; i < CHUNK; ++i) {
        float4 w = __ldcs(reinterpret_cast<const float4*>(Wb + (long long)i * OUT));
        float s = sx[i];
        ax = fmaf(s, w.x, ax);
        ay = fmaf(s, w.y, ay);
        az = fmaf(s, w.z, az);
        aw = fmaf(s, w.w, aw);
    }

    // Single vector atomic (RED.128) instead of 4 scalar REDs.
    float4* y4 = reinterpret_cast<float4*>(y_out + (long long)b * OUT + o4);
    atomicAdd(y4, make_float4(ax, ay, az, aw));

#if defined(__CUDA_ARCH__) && (__CUDA_ARCH__ >= 900)
    // Let the dependent kernel launch as soon as all CTAs reach here.
    cudaTriggerProgrammaticLaunchCompletion();
#endif
}

extern "C" void kernel_launch(void* const* d_in, const int* in_sizes, int n_in,
                              void* d_out, int out_size)
{
    const float* params = (const float*)d_in[0];  // (B, P) fp32
    const float* x      = (const float*)d_in[1];  // (B, 1024) fp32
    float* out          = (float*)d_out;          // (B, 1024) fp32

    float* act1;
    float* act2;
    cudaGetSymbolAddress((void**)&act1, g_act1);
    cudaGetSymbolAddress((void**)&act2, g_act2);

    // No memsets: act1/act2 are zero at load and re-zeroed each pass
    // (layer3 zeroes act1 post-sync, layer1 zeroes act2, layer2 zeroes out).

    cudaLaunchAttribute pdl_attr[1];
    pdl_attr[0].id = cudaLaunchAttributeProgrammaticStreamSerialization;
    pdl_attr[0].val.programmaticStreamSerializationAllowed = 1;

    // Layer 1: 1024 -> 2048. tiles=2, KS=16 (chunk 64) -> 1024 CTAs.
    // ks==0 CTAs also zero act2. No PDL (first kernel).
    {
        dim3 grid(L1 / (256 * 4), BATCH, L0 / 64);
        auto kfn = mlp_layer_splitk<L0, L1, 64, 256, false, BATCH * L2, false, false>;
        kfn<<<grid, 256>>>(params, W1_OFF, B1_OFF, x, act1, act2);
    }
    // Layer 2: 2048 -> 2048. tiles=2, KS=8 (chunk 256) -> 512 CTAs. relu on read.
    // ks==0 CTAs zero `out` pre-sync. PDL on layer 1.
    {
        cudaLaunchConfig_t cfg = {};
        cfg.gridDim  = dim3(L2 / (256 * 4), BATCH, L1 / 256);
        cfg.blockDim = dim3(256, 1, 1);
        cfg.attrs = pdl_attr;
        cfg.numAttrs = 1;
        auto kfn = mlp_layer_splitk<L1, L2, 256, 256, true, BATCH * L3, true, false>;
        cudaLaunchKernelEx(&cfg, kfn, params, W2_OFF, B2_OFF,
                           (const float*)act1, act2, out);
    }
    // Layer 3: 2048 -> 1024. tiles=1, KS=16 (chunk 128) -> 512 CTAs. relu on read.
    // ks==0 CTAs zero act1 POST-sync (act1 is read by layer 2). PDL on layer 2.
    {
        cudaLaunchConfig_t cfg = {};
        cfg.gridDim  = dim3(L3 / (256 * 4), BATCH, L2 / 128);
        cfg.blockDim = dim3(256, 1, 1);
        cfg.attrs = pdl_attr;
        cfg.numAttrs = 1;
        auto kfn = mlp_layer_splitk<L2, L3, 128, 256, true, BATCH * L1, true, true>;
        cudaLaunchKernelEx(&cfg, kfn, params, W3_OFF, B3_OFF,
                           (const float*)act2, out, act1);
    }
}

// round 16
// speedup vs baseline: 1.0286x; 1.0286x over previous
#include <cuda_runtime.h>
#include <cuda_bf16.h>

// Batched per-sample MLP: B=32, 1024 -> 2048 (relu) -> 2048 (relu) -> 1024 (linear)
// HBM-bound GEMV chain at the achievable streaming ceiling (~6.2 TB/s per kernel).
// Round 15: R13 core (best: 156.7us — coarse PDL chaining, fused zero jobs, no
// memsets, __ldcs streaming, unroll 16, float4 vector atomics) with ONE change:
// layer 2 split-K deepened 16 -> 32 (chunk 64, 2048 CTAs) to halve its per-CTA
// duration and thus the two boundary drain/fill tails PDL cannot hide.
// (R14 showed shallower splits lengthen tails and cost ~3us; vector atomics
// make the extra RMW traffic free.)

#define BATCH 32
#define L0 1024
#define L1 2048
#define L2 2048
#define L3 1024

// Per-sample param layout offsets (fp32 elements)
#define W1_OFF 0LL
#define B1_OFF (W1_OFF + (long long)L0 * L1)          // 2097152
#define W2_OFF (B1_OFF + L1)                          // 2099200
#define B2_OFF (W2_OFF + (long long)L1 * L2)          // 6293504
#define W3_OFF (B2_OFF + L2)                          // 6295552
#define B3_OFF (W3_OFF + (long long)L2 * L3)          // 8392704
#define P_LEN  (B3_OFF + L3)                          // 8393728

// Intermediate activations (device globals — zero-initialized at load,
// re-zeroed each pass for graph replay correctness).
__device__ float g_act1[BATCH * L1];
__device__ float g_act2[BATCH * L2];

// One CTA: BLOCK threads, each computing 4 consecutive outputs over a CHUNK of
// the input dimension; partial sums accumulated into y via one float4 atomicAdd.
// RELU_IN : apply relu to x_in while staging (x_in holds pre-activation sums).
// ZERO_N  : element count of z_buf for ks==0 CTAs to zero.
// PDL     : call cudaGridDependencySynchronize() before touching x_in.
// ZERO_POST: zero z_buf AFTER the dependency sync (z_buf is read by the
//            predecessor, so the zero must wait for it — layer3 zeroing act1).
template <int IN, int OUT, int CHUNK, int BLOCK, bool RELU_IN, int ZERO_N,
          bool PDL, bool ZERO_POST>
__global__ void __launch_bounds__(BLOCK)
mlp_layer_splitk(const float* __restrict__ params,
                 long long w_off, long long b_off,
                 const float* __restrict__ x_in,
                 float* __restrict__ y_out,
                 float* __restrict__ z_buf)
{
    __shared__ float sx[CHUNK];

    const int b   = blockIdx.y;
    const int ks  = blockIdx.z;
    const int i0  = ks * CHUNK;
    const int o4  = (blockIdx.x * BLOCK + threadIdx.x) * 4;

    const int nzeroers = gridDim.x * BATCH;
    const int cta_id   = blockIdx.y * gridDim.x + blockIdx.x;

    // Pre-sync side job: zero a buffer the predecessor does NOT read
    // (runs during the predecessor's drain wave under PDL).
    if (ZERO_N > 0 && !ZERO_POST && ks == 0) {
        float4* zb = reinterpret_cast<float4*>(z_buf);
        const int total4 = ZERO_N / 4;
        for (int idx = cta_id * BLOCK + threadIdx.x; idx < total4;
             idx += nzeroers * BLOCK)
            zb[idx] = make_float4(0.f, 0.f, 0.f, 0.f);
    }

    // Pre-sync: bias prefetch (pure input, independent of predecessor).
    float ax = 0.f, ay = 0.f, az = 0.f, aw = 0.f;
    if (ks == 0) {
        const float* __restrict__ Bv = params + (long long)b * P_LEN + b_off + o4;
        float4 bv = __ldg(reinterpret_cast<const float4*>(Bv));
        ax = bv.x; ay = bv.y; az = bv.z; aw = bv.w;
    }

#if defined(__CUDA_ARCH__) && (__CUDA_ARCH__ >= 900)
    if (PDL) cudaGridDependencySynchronize();
#endif

    // Post-sync zero job (buffer was read by the predecessor; sync makes it safe).
    if (ZERO_N > 0 && ZERO_POST && ks == 0) {
        float4* zb = reinterpret_cast<float4*>(z_buf);
        const int total4 = ZERO_N / 4;
        for (int idx = cta_id * BLOCK + threadIdx.x; idx < total4;
             idx += nzeroers * BLOCK)
            zb[idx] = make_float4(0.f, 0.f, 0.f, 0.f);
    }

    // Stage this CTA's input chunk, applying relu if needed.
    const float* __restrict__ xb = x_in + (long long)b * IN + i0;
    for (int i = threadIdx.x; i < CHUNK; i += BLOCK) {
        float v = __ldg(&xb[i]);
        if (RELU_IN) v = fmaxf(v, 0.0f);
        sx[i] = v;
    }
    __syncthreads();

    const float* __restrict__ Wb =
        params + (long long)b * P_LEN + w_off + (long long)i0 * OUT + o4;

    // Inner loop: one streaming LDG.128 per thread per i (512B/warp).
    // __ldcs: W is read exactly once — evict-first keeps L2 for act/bias/atomics.
    #pragma unroll 16
    for (int i = 0; i < CHUNK; ++i) {
        float4 w = __ldcs(reinterpret_cast<const float4*>(Wb + (long long)i * OUT));
        float s = sx[i];
        ax = fmaf(s, w.x, ax);
        ay = fmaf(s, w.y, ay);
        az = fmaf(s, w.z, az);
        aw = fmaf(s, w.w, aw);
    }

    // Single vector atomic (RED.128) instead of 4 scalar REDs.
    float4* y4 = reinterpret_cast<float4*>(y_out + (long long)b * OUT + o4);
    atomicAdd(y4, make_float4(ax, ay, az, aw));

#if defined(__CUDA_ARCH__) && (__CUDA_ARCH__ >= 900)
    // Let the dependent kernel launch as soon as all CTAs reach here.
    cudaTriggerProgrammaticLaunchCompletion();
#endif
}

extern "C" void kernel_launch(void* const* d_in, const int* in_sizes, int n_in,
                              void* d_out, int out_size)
{
    const float* params = (const float*)d_in[0];  // (B, P) fp32
    const float* x      = (const float*)d_in[1];  // (B, 1024) fp32
    float* out          = (float*)d_out;          // (B, 1024) fp32

    float* act1;
    float* act2;
    cudaGetSymbolAddress((void**)&act1, g_act1);
    cudaGetSymbolAddress((void**)&act2, g_act2);

    // No memsets: act1/act2 are zero at load and re-zeroed each pass
    // (layer3 zeroes act1 post-sync, layer1 zeroes act2, layer2 zeroes out).

    cudaLaunchAttribute pdl_attr[1];
    pdl_attr[0].id = cudaLaunchAttributeProgrammaticStreamSerialization;
    pdl_attr[0].val.programmaticStreamSerializationAllowed = 1;

    // Layer 1: 1024 -> 2048. tiles=2, KS=16 (chunk 64) -> 1024 CTAs.
    // ks==0 CTAs also zero act2. No PDL (first kernel).
    {
        dim3 grid(L1 / (256 * 4), BATCH, L0 / 64);
        auto kfn = mlp_layer_splitk<L0, L1, 64, 256, false, BATCH * L2, false, false>;
        kfn<<<grid, 256>>>(params, W1_OFF, B1_OFF, x, act1, act2);
    }
    // Layer 2: 2048 -> 2048. tiles=2, KS=32 (chunk 64) -> 2048 CTAs. relu on read.
    // ks==0 CTAs zero `out` pre-sync. PDL on layer 1.
    {
        cudaLaunchConfig_t cfg = {};
        cfg.gridDim  = dim3(L2 / (256 * 4), BATCH, L1 / 64);
        cfg.blockDim = dim3(256, 1, 1);
        cfg.attrs = pdl_attr;
        cfg.numAttrs = 1;
        auto kfn = mlp_layer_splitk<L1, L2, 64, 256, true, BATCH * L3, true, false>;
        cudaLaunchKernelEx(&cfg, kfn, params, W2_OFF, B2_OFF,
                           (const float*)act1, act2, out);
    }
    // Layer 3: 2048 -> 1024. tiles=1, KS=32 (chunk 64) -> 1024 CTAs. relu on read.
    // ks==0 CTAs zero act1 POST-sync (act1 is read by layer 2). PDL on layer 2.
    {
        cudaLaunchConfig_t cfg = {};
        cfg.gridDim  = dim3(L3 / (256 * 4), BATCH, L2 / 64);
        cfg.blockDim = dim3(256, 1, 1);
        cfg.attrs = pdl_attr;
        cfg.numAttrs = 1;
        auto kfn = mlp_layer_splitk<L2, L3, 64, 256, true, BATCH * L1, true, true>;
        cudaLaunchKernelEx(&cfg, kfn, params, W3_OFF, B3_OFF,
                           (const float*)act2, out, act1);
    }
}

// round 17
// speedup vs baseline: 1.0355x; 1.0066x over previous
#include <cuda_runtime.h>
#include <cuda_bf16.h>

// Batched per-sample MLP: B=32, 1024 -> 2048 (relu) -> 2048 (relu) -> 1024 (linear)
// HBM-bound GEMV chain at the achievable streaming ceiling (~6.2 TB/s per kernel).
// Round 16: R15 core (155.4us — coarse PDL chaining, fused zero jobs, no memsets,
// __ldcs streaming, unroll 16, float4 vector atomics, layer-2 chunk 64) + the
// same validated knob applied to layers 1 and 3: chunk 64 -> 32 (2048 CTAs each),
// halving their per-CTA durations and therefore the boundary fill/drain tails
// that PDL cannot hide. (R14/R15 established: tails scale with per-CTA duration;
// streaming rate and RED.128 cost are split-invariant.)

#define BATCH 32
#define L0 1024
#define L1 2048
#define L2 2048
#define L3 1024

// Per-sample param layout offsets (fp32 elements)
#define W1_OFF 0LL
#define B1_OFF (W1_OFF + (long long)L0 * L1)          // 2097152
#define W2_OFF (B1_OFF + L1)                          // 2099200
#define B2_OFF (W2_OFF + (long long)L1 * L2)          // 6293504
#define W3_OFF (B2_OFF + L2)                          // 6295552
#define B3_OFF (W3_OFF + (long long)L2 * L3)          // 8392704
#define P_LEN  (B3_OFF + L3)                          // 8393728

// Intermediate activations (device globals — zero-initialized at load,
// re-zeroed each pass for graph replay correctness).
__device__ float g_act1[BATCH * L1];
__device__ float g_act2[BATCH * L2];

// One CTA: BLOCK threads, each computing 4 consecutive outputs over a CHUNK of
// the input dimension; partial sums accumulated into y via one float4 atomicAdd.
// RELU_IN : apply relu to x_in while staging (x_in holds pre-activation sums).
// ZERO_N  : element count of z_buf for ks==0 CTAs to zero.
// PDL     : call cudaGridDependencySynchronize() before touching x_in.
// ZERO_POST: zero z_buf AFTER the dependency sync (z_buf is read by the
//            predecessor, so the zero must wait for it — layer3 zeroing act1).
template <int IN, int OUT, int CHUNK, int BLOCK, bool RELU_IN, int ZERO_N,
          bool PDL, bool ZERO_POST>
__global__ void __launch_bounds__(BLOCK)
mlp_layer_splitk(const float* __restrict__ params,
                 long long w_off, long long b_off,
                 const float* __restrict__ x_in,
                 float* __restrict__ y_out,
                 float* __restrict__ z_buf)
{
    __shared__ float sx[CHUNK];

    const int b   = blockIdx.y;
    const int ks  = blockIdx.z;
    const int i0  = ks * CHUNK;
    const int o4  = (blockIdx.x * BLOCK + threadIdx.x) * 4;

    const int nzeroers = gridDim.x * BATCH;
    const int cta_id   = blockIdx.y * gridDim.x + blockIdx.x;

    // Pre-sync side job: zero a buffer the predecessor does NOT read
    // (runs during the predecessor's drain wave under PDL).
    if (ZERO_N > 0 && !ZERO_POST && ks == 0) {
        float4* zb = reinterpret_cast<float4*>(z_buf);
        const int total4 = ZERO_N / 4;
        for (int idx = cta_id * BLOCK + threadIdx.x; idx < total4;
             idx += nzeroers * BLOCK)
            zb[idx] = make_float4(0.f, 0.f, 0.f, 0.f);
    }

    // Pre-sync: bias prefetch (pure input, independent of predecessor).
    float ax = 0.f, ay = 0.f, az = 0.f, aw = 0.f;
    if (ks == 0) {
        const float* __restrict__ Bv = params + (long long)b * P_LEN + b_off + o4;
        float4 bv = __ldg(reinterpret_cast<const float4*>(Bv));
        ax = bv.x; ay = bv.y; az = bv.z; aw = bv.w;
    }

#if defined(__CUDA_ARCH__) && (__CUDA_ARCH__ >= 900)
    if (PDL) cudaGridDependencySynchronize();
#endif

    // Post-sync zero job (buffer was read by the predecessor; sync makes it safe).
    if (ZERO_N > 0 && ZERO_POST && ks == 0) {
        float4* zb = reinterpret_cast<float4*>(z_buf);
        const int total4 = ZERO_N / 4;
        for (int idx = cta_id * BLOCK + threadIdx.x; idx < total4;
             idx += nzeroers * BLOCK)
            zb[idx] = make_float4(0.f, 0.f, 0.f, 0.f);
    }

    // Stage this CTA's input chunk, applying relu if needed.
    const float* __restrict__ xb = x_in + (long long)b * IN + i0;
    for (int i = threadIdx.x; i < CHUNK; i += BLOCK) {
        float v = __ldg(&xb[i]);
        if (RELU_IN) v = fmaxf(v, 0.0f);
        sx[i] = v;
    }
    __syncthreads();

    const float* __restrict__ Wb =
        params + (long long)b * P_LEN + w_off + (long long)i0 * OUT + o4;

    // Inner loop: one streaming LDG.128 per thread per i (512B/warp).
    // __ldcs: W is read exactly once — evict-first keeps L2 for act/bias/atomics.
    #pragma unroll 16
    for (int i = 0; i < CHUNK; ++i) {
        float4 w = __ldcs(reinterpret_cast<const float4*>(Wb + (long long)i * OUT));
        float s = sx[i];
        ax = fmaf(s, w.x, ax);
        ay = fmaf(s, w.y, ay);
        az = fmaf(s, w.z, az);
        aw = fmaf(s, w.w, aw);
    }

    // Single vector atomic (RED.128) instead of 4 scalar REDs.
    float4* y4 = reinterpret_cast<float4*>(y_out + (long long)b * OUT + o4);
    atomicAdd(y4, make_float4(ax, ay, az, aw));

#if defined(__CUDA_ARCH__) && (__CUDA_ARCH__ >= 900)
    // Let the dependent kernel launch as soon as all CTAs reach here.
    cudaTriggerProgrammaticLaunchCompletion();
#endif
}

extern "C" void kernel_launch(void* const* d_in, const int* in_sizes, int n_in,
                              void* d_out, int out_size)
{
    const float* params = (const float*)d_in[0];  // (B, P) fp32
    const float* x      = (const float*)d_in[1];  // (B, 1024) fp32
    float* out          = (float*)d_out;          // (B, 1024) fp32

    float* act1;
    float* act2;
    cudaGetSymbolAddress((void**)&act1, g_act1);
    cudaGetSymbolAddress((void**)&act2, g_act2);

    // No memsets: act1/act2 are zero at load and re-zeroed each pass
    // (layer3 zeroes act1 post-sync, layer1 zeroes act2, layer2 zeroes out).

    cudaLaunchAttribute pdl_attr[1];
    pdl_attr[0].id = cudaLaunchAttributeProgrammaticStreamSerialization;
    pdl_attr[0].val.programmaticStreamSerializationAllowed = 1;

    // Layer 1: 1024 -> 2048. tiles=2, KS=32 (chunk 32) -> 2048 CTAs.
    // ks==0 CTAs also zero act2. No PDL (first kernel).
    {
        dim3 grid(L1 / (256 * 4), BATCH, L0 / 32);
        auto kfn = mlp_layer_splitk<L0, L1, 32, 256, false, BATCH * L2, false, false>;
        kfn<<<grid, 256>>>(params, W1_OFF, B1_OFF, x, act1, act2);
    }
    // Layer 2: 2048 -> 2048. tiles=2, KS=32 (chunk 64) -> 2048 CTAs. relu on read.
    // ks==0 CTAs zero `out` pre-sync. PDL on layer 1.
    {
        cudaLaunchConfig_t cfg = {};
        cfg.gridDim  = dim3(L2 / (256 * 4), BATCH, L1 / 64);
        cfg.blockDim = dim3(256, 1, 1);
        cfg.attrs = pdl_attr;
        cfg.numAttrs = 1;
        auto kfn = mlp_layer_splitk<L1, L2, 64, 256, true, BATCH * L3, true, false>;
        cudaLaunchKernelEx(&cfg, kfn, params, W2_OFF, B2_OFF,
                           (const float*)act1, act2, out);
    }
    // Layer 3: 2048 -> 1024. tiles=1, KS=64 (chunk 32) -> 2048 CTAs. relu on read.
    // ks==0 CTAs zero act1 POST-sync (act1 is read by layer 2). PDL on layer 2.
    {
        cudaLaunchConfig_t cfg = {};
        cfg.gridDim  = dim3(L3 / (256 * 4), BATCH, L2 / 32);
        cfg.blockDim = dim3(256, 1, 1);
        cfg.attrs = pdl_attr;
        cfg.numAttrs = 1;
        auto kfn = mlp_layer_splitk<L2, L3, 32, 256, true, BATCH * L1, true, true>;
        cudaLaunchKernelEx(&cfg, kfn, params, W3_OFF, B3_OFF,
                           (const float*)act2, out, act1);
    }
}